// round 1
// baseline (speedup 1.0000x reference)
#include <cuda_runtime.h>
#include <cstdint>

#define Nn 32
#define Cc 256
#define Hh 32
#define Ww 32
#define HW (Hh*Ww)
#define NCHW (Nn*Cc*Hh*Ww)
#define NPIX (Nn*Hh*Ww)
#define NCHUNK 36

// ---------------- scratch (device globals; no allocation) ----------------
__device__ uint32_t           g_xbits[NPIX*8];        // channel-packed sign bits of current conv input
__device__ uint32_t           g_wchan[2][Cc*72];      // channel-packed weights [o][j=0..8][k=0..7]
__device__ unsigned long long g_wrT[2][NCHUNK*Cc];    // r-packed weights, transposed [chunk][o]
__device__ int16_t            g_y1[NCHW];             // conv1 output (clipped int)
__device__ float              g_z[NCHW];              // conv2 output + residual
__device__ long long          g_s1[Cc], g_q1[Cc];     // conv1 channel stats (exact int64)
__device__ float              g_A1[Cc], g_B1[Cc];     // bn1 sign-test coefs
__device__ double             g_p1[Cc*Nn], g_p2[Cc*Nn]; // bn2 partial sums (deterministic)
__device__ float              g_A2[Cc], g_B2[Cc];
__device__ unsigned long long g_vmask[9*NCHUNK];      // per boundary-class valid-bit mask per chunk
__device__ int                g_V[9*NCHUNK];          // valid counts
__device__ float              g_regbase;              // 3*G/1024

// ---------------- init: geometric tables + stat reset + regularizer ----------------
__global__ void k_init() {
    int t = threadIdx.x;
    if (t < 9*NCHUNK) {
        int cls = t / NCHUNK, i = t % NCHUNK;
        int ht = cls / 3, wt = cls % 3;
        int r = 64*i, c = r/9, j = r - 9*c;
        unsigned long long m = 0;
        for (int b = 0; b < 64; b++) {
            int kh = j/3, kw = j - 3*kh;
            bool inval = (ht==0 && kh==0) || (ht==2 && kh==2) ||
                         (wt==0 && kw==0) || (wt==2 && kw==2);
            if (!inval) m |= 1ull << b;
            if (++j == 9) { j = 0; c++; }
        }
        g_vmask[t] = m;
        g_V[t] = __popcll(m);
    }
    if (t < Cc) { g_s1[t] = 0; g_q1[t] = 0; }
    __syncthreads();
    if (t == 0) {
        // reg = r1 + 2*r2 = 3 * sum_{chunks,pixels} parity / (H*W); parity is geometric
        long long G = 0;
        int npix[3] = {1, 30, 1};
        for (int cls = 0; cls < 9; cls++) {
            long long cnt = (long long)npix[cls/3] * npix[cls%3];
            for (int i = 0; i < NCHUNK; i++)
                G += cnt * (long long)(g_V[cls*NCHUNK + i] & 1);
        }
        g_regbase = 3.0f * (float)G / (float)HW;
    }
}

// ---------------- weight packing ----------------
// channel-packed: bit (c&31) of word [o][j][c>>5] = sign(w[o, c, kh, kw])
__global__ void k_packw_chan(const float* __restrict__ w, int slot) {
    int t = blockIdx.x * blockDim.x + threadIdx.x;
    if (t >= Cc*72) return;
    int o = t / 72, rem = t % 72, j = rem / 8, k = rem % 8;
    const float* base = w + o*2304 + j;
    uint32_t word = 0;
    #pragma unroll 8
    for (int cc = 0; cc < 32; cc++) {
        int c = k*32 + cc;
        if (base[c*9] >= 0.f) word |= 1u << cc;
    }
    g_wchan[slot][t] = word;
}

// r-packed transposed: bit b of word [i][o] = sign(w[o, r=64i+b])   (w flat layout IS r-order)
__global__ void k_packw_r(const float* __restrict__ w, int slot) {
    int o = blockIdx.x;
    int warp = threadIdx.x >> 5, lane = threadIdx.x & 31;
    for (int i = warp; i < NCHUNK; i += 8) {
        unsigned lo = __ballot_sync(0xffffffffu, w[o*2304 + 64*i + lane]      >= 0.f);
        unsigned hi = __ballot_sync(0xffffffffu, w[o*2304 + 64*i + 32 + lane] >= 0.f);
        if (lane == 0)
            g_wrT[slot][i*Cc + o] = (unsigned long long)lo | ((unsigned long long)hi << 32);
    }
}

// ---------------- input packing ----------------
__global__ void k_pack_x(const float* __restrict__ x) {
    int n = blockIdx.x >> 5, h = blockIdx.x & 31;
    int w = threadIdx.x & 31, k = threadIdx.x >> 5;
    const float* base = x + ((size_t)(n*Cc + k*32) * Hh + h) * Ww + w;
    uint32_t word = 0;
    #pragma unroll 8
    for (int cc = 0; cc < 32; cc++)
        if (base[(size_t)cc * HW] >= 0.f) word |= 1u << cc;
    g_xbits[((n*Hh + h)*Ww + w)*8 + k] = word;
}

// pack sign of bn1(hardtanh preserves sign): bit = (y*A1[c] + B1[c] >= 0)
__global__ void k_pack2() {
    int n = blockIdx.x >> 5, h = blockIdx.x & 31;
    int w = threadIdx.x & 31, k = threadIdx.x >> 5;
    const int16_t* base = g_y1 + ((size_t)(n*Cc + k*32) * Hh + h) * Ww + w;
    uint32_t word = 0;
    #pragma unroll 8
    for (int cc = 0; cc < 32; cc++) {
        int c = k*32 + cc;
        float y = (float)base[(size_t)cc * HW];
        if (fmaf(y, g_A1[c], g_B1[c]) >= 0.f) word |= 1u << cc;
    }
    g_xbits[((n*Hh + h)*Ww + w)*8 + k] = word;
}

// ---------------- interior conv: plain XNOR-popcount (quantization is exact no-op) ----------------
template<int MODE>   // 1: write y1 int16; 2: write z = clipped + residual
__global__ void k_conv_int(const float* __restrict__ x0res, int slot) {
    int n = blockIdx.x / 30, h = 1 + blockIdx.x % 30;
    __shared__ __align__(16) uint32_t sx[3][Ww][8];
    int t = threadIdx.x;
    if (t < 192) {   // 3 rows * 64 uint4
        int r = t >> 6, q = t & 63;
        ((uint4*)sx)[t] = ((const uint4*)(g_xbits + (size_t)(n*Hh + (h-1+r)) * Ww * 8))[q];
    }
    __syncthreads();
    int w = t & 31, warp = t >> 5;
    int wl = (w > 0)  ? w-1 : 0;
    int wr = (w < 31) ? w+1 : 31;
    const int wcol[3] = {wl, w, wr};
    for (int og = 0; og < 32; og++) {
        int o = og*8 + warp;
        const uint4* wp = (const uint4*)(&g_wchan[slot][o*72]);
        int s = 0;
        #pragma unroll
        for (int j = 0; j < 9; j++) {
            int rr = j / 3;
            int wc = wcol[j % 3];
            const uint32_t* xp = &sx[rr][wc][0];
            uint4 xa = *(const uint4*)xp;
            uint4 xb = *(const uint4*)(xp + 4);
            uint4 wa = __ldg(wp + 2*j);
            uint4 wb = __ldg(wp + 2*j + 1);
            s += __popc(xa.x ^ wa.x) + __popc(xa.y ^ wa.y)
               + __popc(xa.z ^ wa.z) + __popc(xa.w ^ wa.w)
               + __popc(xb.x ^ wb.x) + __popc(xb.y ^ wb.y)
               + __popc(xb.z ^ wb.z) + __popc(xb.w ^ wb.w);
        }
        int acc = 2304 - 2*s;
        acc = min(max(acc, -254), 254);
        if (w >= 1 && w <= 30) {
            size_t idx = ((size_t)(n*Cc + o) * Hh + h) * Ww + w;
            if (MODE == 1) g_y1[idx] = (int16_t)acc;
            else           g_z[idx]  = (float)acc + x0res[idx];
        }
    }
}

// ---------------- boundary conv: exact chunked psum with banker's-rounding quantizer ----------------
template<int MODE>
__global__ void k_conv_bnd(const float* __restrict__ x0res, int slot) {
    int n = blockIdx.x / 124, b = blockIdx.x % 124;
    int h, w;
    if      (b < 32) { h = 0;      w = b; }
    else if (b < 64) { h = 31;     w = b - 32; }
    else if (b < 94) { w = 0;      h = b - 63; }
    else             { w = 31;     h = b - 93; }
    int ht  = (h == 0) ? 0 : ((h == 31) ? 2 : 1);
    int wt  = (w == 0) ? 0 : ((w == 31) ? 2 : 1);
    int cls = ht*3 + wt;

    __shared__ unsigned long long sxr[NCHUNK];
    __shared__ int soff[9];
    int t = threadIdx.x;
    if (t < 9) {
        int kh = t / 3, kw = t % 3;
        int hh = min(max(h + kh - 1, 0), 31);
        int ww = min(max(w + kw - 1, 0), 31);
        soff[t] = ((n*Hh + hh)*Ww + ww) * 8;
    }
    __syncthreads();
    if (t < NCHUNK) {   // build r-ordered bit word for this chunk (content at invalid taps masked later)
        int i = t, r = 64*i, c = r/9, j = r - 9*c;
        unsigned long long word = 0;
        for (int bb = 0; bb < 64; bb++) {
            uint32_t xw = g_xbits[soff[j] + (c >> 5)];
            word |= (unsigned long long)((xw >> (c & 31)) & 1u) << bb;
            if (++j == 9) { j = 0; c++; }
        }
        sxr[i] = word;
    }
    __syncthreads();

    int o = t;   // 256 threads = 256 output channels
    int acc = 0;
    #pragma unroll 4
    for (int i = 0; i < NCHUNK; i++) {
        unsigned long long X = (sxr[i] ^ g_wrT[slot][i*Cc + o]) & g_vmask[cls*NCHUNK + i];
        int psum = g_V[cls*NCHUNK + i] - 2*__popcll(X);
        int rmod = psum & 3;                   // two's-complement mod 4
        psum += (rmod == 3) - (rmod == 1);     // round-half-to-even of psum/2, *2
        acc += psum;
    }
    acc = min(max(acc, -254), 254);
    size_t idx = ((size_t)(n*Cc + o) * Hh + h) * Ww + w;
    if (MODE == 1) g_y1[idx] = (int16_t)acc;
    else           g_z[idx]  = (float)acc + x0res[idx];
}

// ---------------- BN1 stats (exact integer; atomics are order-independent) ----------------
__global__ void k_stats1() {
    int o = blockIdx.x >> 5, n = blockIdx.x & 31;
    const int16_t* base = g_y1 + (size_t)(n*Cc + o) * HW;
    int t = threadIdx.x;
    int s = 0, q = 0;
    for (int k = t; k < HW; k += 256) { int v = base[k]; s += v; q += v*v; }
    __shared__ int ss[256], sq[256];
    ss[t] = s; sq[t] = q; __syncthreads();
    for (int st = 128; st > 0; st >>= 1) {
        if (t < st) { ss[t] += ss[t+st]; sq[t] += sq[t+st]; }
        __syncthreads();
    }
    if (t == 0) {
        atomicAdd((unsigned long long*)&g_s1[o], (unsigned long long)(long long)ss[0]);
        atomicAdd((unsigned long long*)&g_q1[o], (unsigned long long)(long long)sq[0]);
    }
}

__global__ void k_coef1(const float* __restrict__ gamma, const float* __restrict__ beta) {
    int o = threadIdx.x;
    double m   = (double)g_s1[o] / (double)(Nn*HW);
    double var = (double)g_q1[o] / (double)(Nn*HW) - m*m;
    float inv  = (float)(1.0 / sqrt(var + 1e-5));
    float A = gamma[o] * inv;
    g_A1[o] = A;
    g_B1[o] = beta[o] - (float)m * A;
}

// ---------------- BN2 stats (two-stage, deterministic order) ----------------
__global__ void k_stats2a() {
    int o = blockIdx.x >> 5, n = blockIdx.x & 31;
    const float* base = g_z + (size_t)(n*Cc + o) * HW;
    int t = threadIdx.x;
    double s = 0, q = 0;
    for (int k = t; k < HW; k += 256) { double v = (double)base[k]; s += v; q += v*v; }
    __shared__ double ss[256], sq[256];
    ss[t] = s; sq[t] = q; __syncthreads();
    for (int st = 128; st > 0; st >>= 1) {
        if (t < st) { ss[t] += ss[t+st]; sq[t] += sq[t+st]; }
        __syncthreads();
    }
    if (t == 0) { g_p1[blockIdx.x] = ss[0]; g_p2[blockIdx.x] = sq[0]; }
}

__global__ void k_coef2(const float* __restrict__ gamma, const float* __restrict__ beta) {
    int o = threadIdx.x;
    double s = 0, q = 0;
    for (int n = 0; n < Nn; n++) { s += g_p1[o*32 + n]; q += g_p2[o*32 + n]; }
    double m   = s / (double)(Nn*HW);
    double var = q / (double)(Nn*HW) - m*m;
    float inv  = (float)(1.0 / sqrt(var + 1e-5));
    float A = gamma[o] * inv;
    g_A2[o] = A;
    g_B2[o] = beta[o] - (float)m * A;
}

// ---------------- finalize: bn2 + hardtanh + regularizer scalar ----------------
__global__ void k_final(float* __restrict__ out, const float* __restrict__ reg0, int out_size) {
    size_t idx = (size_t)blockIdx.x * 256 + threadIdx.x;
    if (idx < (size_t)NCHW) {
        int o = (int)((idx >> 10) & 255);
        float v = fmaf(g_z[idx], g_A2[o], g_B2[o]);
        v = fminf(fmaxf(v, -1.f), 1.f);
        out[idx] = v;
    }
    if (idx == 0) out[out_size - 1] = reg0[0] + g_regbase;
}

// ---------------- launch ----------------
extern "C" void kernel_launch(void* const* d_in, const int* in_sizes, int n_in,
                              void* d_out, int out_size) {
    const float* x0   = (const float*)d_in[0];
    const float* reg0 = (const float*)d_in[1];
    const float* w1   = (const float*)d_in[2];
    const float* g1   = (const float*)d_in[3];
    const float* b1   = (const float*)d_in[4];
    const float* w2   = (const float*)d_in[5];
    const float* g2   = (const float*)d_in[6];
    const float* b2   = (const float*)d_in[7];
    float* out = (float*)d_out;

    k_init<<<1, 512>>>();
    k_packw_chan<<<72, 256>>>(w1, 0);
    k_packw_chan<<<72, 256>>>(w2, 1);
    k_packw_r<<<256, 256>>>(w1, 0);
    k_packw_r<<<256, 256>>>(w2, 1);
    k_pack_x<<<Nn*Hh, 256>>>(x0);

    k_conv_int<1><<<Nn*30, 256>>>(nullptr, 0);
    k_conv_bnd<1><<<Nn*124, 256>>>(nullptr, 0);
    k_stats1<<<Cc*Nn, 256>>>();
    k_coef1<<<1, Cc>>>(g1, b1);
    k_pack2<<<Nn*Hh, 256>>>();

    k_conv_int<2><<<Nn*30, 256>>>(x0, 1);
    k_conv_bnd<2><<<Nn*124, 256>>>(x0, 1);
    k_stats2a<<<Cc*Nn, 256>>>();
    k_coef2<<<1, Cc>>>(g2, b2);

    k_final<<<(NCHW + 255) / 256, 256>>>(out, reg0, out_size);
}

// round 2
// speedup vs baseline: 1.0011x; 1.0011x over previous
#include <cuda_runtime.h>
#include <cstdint>

#define Nn 32
#define Cc 256
#define Hh 32
#define Ww 32
#define HW (Hh*Ww)
#define NCHW (Nn*Cc*Hh*Ww)
#define NPIX (Nn*Hh*Ww)
#define NCHUNK 36

// ---------------- scratch (device globals; no allocation) ----------------
__device__ uint32_t           g_xbits[NPIX*8];        // channel-packed sign bits of current conv input
__device__ uint32_t           g_wchan[2][Cc*72];      // channel-packed weights [o][j=0..8][k=0..7]
__device__ unsigned long long g_wrT[2][NCHUNK*Cc];    // r-packed weights, transposed [chunk][o]
__device__ int16_t            g_y1[NCHW];             // conv1 output (clipped int)
__device__ float              g_z[NCHW];              // conv2 output + residual
__device__ long long          g_s1[Cc], g_q1[Cc];     // conv1 channel stats (exact int64)
__device__ float              g_A1[Cc], g_B1[Cc];     // bn1 sign-test coefs
__device__ double             g_p1[Cc*Nn], g_p2[Cc*Nn]; // bn2 partial sums (deterministic)
__device__ float              g_A2[Cc], g_B2[Cc];
__device__ unsigned long long g_vmask[9*NCHUNK];      // per boundary-class valid-bit mask per chunk
__device__ int                g_V[9*NCHUNK];          // valid counts
__device__ float              g_regbase;              // 3*G/1024

// ---------------- init: geometric tables + stat reset + regularizer ----------------
__global__ void k_init() {
    int t = threadIdx.x;
    if (t < 9*NCHUNK) {
        int cls = t / NCHUNK, i = t % NCHUNK;
        int ht = cls / 3, wt = cls % 3;
        int r = 64*i, c = r/9, j = r - 9*c;
        unsigned long long m = 0;
        for (int b = 0; b < 64; b++) {
            int kh = j/3, kw = j - 3*kh;
            bool inval = (ht==0 && kh==0) || (ht==2 && kh==2) ||
                         (wt==0 && kw==0) || (wt==2 && kw==2);
            if (!inval) m |= 1ull << b;
            if (++j == 9) { j = 0; c++; }
        }
        g_vmask[t] = m;
        g_V[t] = __popcll(m);
    }
    if (t < Cc) { g_s1[t] = 0; g_q1[t] = 0; }
    __syncthreads();
    if (t == 0) {
        // reg = r1 + 2*r2 = 3 * sum_{chunks,pixels} parity / (H*W); parity is geometric
        long long G = 0;
        int npix[3] = {1, 30, 1};
        for (int cls = 0; cls < 9; cls++) {
            long long cnt = (long long)npix[cls/3] * npix[cls%3];
            for (int i = 0; i < NCHUNK; i++)
                G += cnt * (long long)(g_V[cls*NCHUNK + i] & 1);
        }
        g_regbase = 3.0f * (float)G / (float)HW;
    }
}

// ---------------- weight packing ----------------
// channel-packed: bit (c&31) of word [o][j][c>>5] = sign(w[o, c, kh, kw])
__global__ void k_packw_chan(const float* __restrict__ w, int slot) {
    int t = blockIdx.x * blockDim.x + threadIdx.x;
    if (t >= Cc*72) return;
    int o = t / 72, rem = t % 72, j = rem / 8, k = rem % 8;
    const float* base = w + o*2304 + j;
    uint32_t word = 0;
    #pragma unroll 8
    for (int cc = 0; cc < 32; cc++) {
        int c = k*32 + cc;
        if (base[c*9] >= 0.f) word |= 1u << cc;
    }
    g_wchan[slot][t] = word;
}

// r-packed transposed: bit b of word [i][o] = sign(w[o, r=64i+b])   (w flat layout IS r-order)
__global__ void k_packw_r(const float* __restrict__ w, int slot) {
    int o = blockIdx.x;
    int warp = threadIdx.x >> 5, lane = threadIdx.x & 31;
    for (int i = warp; i < NCHUNK; i += 8) {
        unsigned lo = __ballot_sync(0xffffffffu, w[o*2304 + 64*i + lane]      >= 0.f);
        unsigned hi = __ballot_sync(0xffffffffu, w[o*2304 + 64*i + 32 + lane] >= 0.f);
        if (lane == 0)
            g_wrT[slot][i*Cc + o] = (unsigned long long)lo | ((unsigned long long)hi << 32);
    }
}

// ---------------- input packing ----------------
__global__ void k_pack_x(const float* __restrict__ x) {
    int n = blockIdx.x >> 5, h = blockIdx.x & 31;
    int w = threadIdx.x & 31, k = threadIdx.x >> 5;
    const float* base = x + ((size_t)(n*Cc + k*32) * Hh + h) * Ww + w;
    uint32_t word = 0;
    #pragma unroll 8
    for (int cc = 0; cc < 32; cc++)
        if (base[(size_t)cc * HW] >= 0.f) word |= 1u << cc;
    g_xbits[((n*Hh + h)*Ww + w)*8 + k] = word;
}

// pack sign of bn1(hardtanh preserves sign): bit = (y*A1[c] + B1[c] >= 0)
__global__ void k_pack2() {
    int n = blockIdx.x >> 5, h = blockIdx.x & 31;
    int w = threadIdx.x & 31, k = threadIdx.x >> 5;
    const int16_t* base = g_y1 + ((size_t)(n*Cc + k*32) * Hh + h) * Ww + w;
    uint32_t word = 0;
    #pragma unroll 8
    for (int cc = 0; cc < 32; cc++) {
        int c = k*32 + cc;
        float y = (float)base[(size_t)cc * HW];
        if (fmaf(y, g_A1[c], g_B1[c]) >= 0.f) word |= 1u << cc;
    }
    g_xbits[((n*Hh + h)*Ww + w)*8 + k] = word;
}

// ---------------- interior conv: plain XNOR-popcount (quantization is exact no-op) ----------------
template<int MODE>   // 1: write y1 int16; 2: write z = clipped + residual
__global__ void k_conv_int(const float* __restrict__ x0res, int slot) {
    int n = blockIdx.x / 30, h = 1 + blockIdx.x % 30;
    __shared__ __align__(16) uint32_t sx[3][Ww][8];
    int t = threadIdx.x;
    if (t < 192) {   // 3 rows * 64 uint4
        int r = t >> 6, q = t & 63;
        ((uint4*)sx)[t] = ((const uint4*)(g_xbits + (size_t)(n*Hh + (h-1+r)) * Ww * 8))[q];
    }
    __syncthreads();
    int w = t & 31, warp = t >> 5;
    int wl = (w > 0)  ? w-1 : 0;
    int wr = (w < 31) ? w+1 : 31;
    const int wcol[3] = {wl, w, wr};
    for (int og = 0; og < 32; og++) {
        int o = og*8 + warp;
        const uint4* wp = (const uint4*)(&g_wchan[slot][o*72]);
        int s = 0;
        #pragma unroll
        for (int j = 0; j < 9; j++) {
            int rr = j / 3;
            int wc = wcol[j % 3];
            const uint32_t* xp = &sx[rr][wc][0];
            uint4 xa = *(const uint4*)xp;
            uint4 xb = *(const uint4*)(xp + 4);
            uint4 wa = __ldg(wp + 2*j);
            uint4 wb = __ldg(wp + 2*j + 1);
            s += __popc(xa.x ^ wa.x) + __popc(xa.y ^ wa.y)
               + __popc(xa.z ^ wa.z) + __popc(xa.w ^ wa.w)
               + __popc(xb.x ^ wb.x) + __popc(xb.y ^ wb.y)
               + __popc(xb.z ^ wb.z) + __popc(xb.w ^ wb.w);
        }
        int acc = 2304 - 2*s;
        acc = min(max(acc, -254), 254);
        if (w >= 1 && w <= 30) {
            size_t idx = ((size_t)(n*Cc + o) * Hh + h) * Ww + w;
            if (MODE == 1) g_y1[idx] = (int16_t)acc;
            else           g_z[idx]  = (float)acc + x0res[idx];
        }
    }
}

// ---------------- boundary conv: exact chunked psum with banker's-rounding quantizer ----------------
template<int MODE>
__global__ void k_conv_bnd(const float* __restrict__ x0res, int slot) {
    int n = blockIdx.x / 124, b = blockIdx.x % 124;
    int h, w;
    if      (b < 32) { h = 0;      w = b; }
    else if (b < 64) { h = 31;     w = b - 32; }
    else if (b < 94) { w = 0;      h = b - 63; }
    else             { w = 31;     h = b - 93; }
    int ht  = (h == 0) ? 0 : ((h == 31) ? 2 : 1);
    int wt  = (w == 0) ? 0 : ((w == 31) ? 2 : 1);
    int cls = ht*3 + wt;

    __shared__ unsigned long long sxr[NCHUNK];
    __shared__ int soff[9];
    int t = threadIdx.x;
    if (t < 9) {
        int kh = t / 3, kw = t % 3;
        int hh = min(max(h + kh - 1, 0), 31);
        int ww = min(max(w + kw - 1, 0), 31);
        soff[t] = ((n*Hh + hh)*Ww + ww) * 8;
    }
    __syncthreads();
    if (t < NCHUNK) {   // build r-ordered bit word for this chunk (content at invalid taps masked later)
        int i = t, r = 64*i, c = r/9, j = r - 9*c;
        unsigned long long word = 0;
        for (int bb = 0; bb < 64; bb++) {
            uint32_t xw = g_xbits[soff[j] + (c >> 5)];
            word |= (unsigned long long)((xw >> (c & 31)) & 1u) << bb;
            if (++j == 9) { j = 0; c++; }
        }
        sxr[i] = word;
    }
    __syncthreads();

    int o = t;   // 256 threads = 256 output channels
    int acc = 0;
    #pragma unroll 4
    for (int i = 0; i < NCHUNK; i++) {
        unsigned long long X = (sxr[i] ^ g_wrT[slot][i*Cc + o]) & g_vmask[cls*NCHUNK + i];
        int psum = g_V[cls*NCHUNK + i] - 2*__popcll(X);
        int rmod = psum & 3;                   // two's-complement mod 4
        psum += (rmod == 3) - (rmod == 1);     // round-half-to-even of psum/2, *2
        acc += psum;
    }
    acc = min(max(acc, -254), 254);
    size_t idx = ((size_t)(n*Cc + o) * Hh + h) * Ww + w;
    if (MODE == 1) g_y1[idx] = (int16_t)acc;
    else           g_z[idx]  = (float)acc + x0res[idx];
}

// ---------------- BN1 stats (exact integer; atomics are order-independent) ----------------
__global__ void k_stats1() {
    int o = blockIdx.x >> 5, n = blockIdx.x & 31;
    const int16_t* base = g_y1 + (size_t)(n*Cc + o) * HW;
    int t = threadIdx.x;
    int s = 0, q = 0;
    for (int k = t; k < HW; k += 256) { int v = base[k]; s += v; q += v*v; }
    __shared__ int ss[256], sq[256];
    ss[t] = s; sq[t] = q; __syncthreads();
    for (int st = 128; st > 0; st >>= 1) {
        if (t < st) { ss[t] += ss[t+st]; sq[t] += sq[t+st]; }
        __syncthreads();
    }
    if (t == 0) {
        atomicAdd((unsigned long long*)&g_s1[o], (unsigned long long)(long long)ss[0]);
        atomicAdd((unsigned long long*)&g_q1[o], (unsigned long long)(long long)sq[0]);
    }
}

__global__ void k_coef1(const float* __restrict__ gamma, const float* __restrict__ beta) {
    int o = threadIdx.x;
    double m   = (double)g_s1[o] / (double)(Nn*HW);
    double var = (double)g_q1[o] / (double)(Nn*HW) - m*m;
    float inv  = (float)(1.0 / sqrt(var + 1e-5));
    float A = gamma[o] * inv;
    g_A1[o] = A;
    g_B1[o] = beta[o] - (float)m * A;
}

// ---------------- BN2 stats (two-stage, deterministic order) ----------------
__global__ void k_stats2a() {
    int o = blockIdx.x >> 5, n = blockIdx.x & 31;
    const float* base = g_z + (size_t)(n*Cc + o) * HW;
    int t = threadIdx.x;
    double s = 0, q = 0;
    for (int k = t; k < HW; k += 256) { double v = (double)base[k]; s += v; q += v*v; }
    __shared__ double ss[256], sq[256];
    ss[t] = s; sq[t] = q; __syncthreads();
    for (int st = 128; st > 0; st >>= 1) {
        if (t < st) { ss[t] += ss[t+st]; sq[t] += sq[t+st]; }
        __syncthreads();
    }
    if (t == 0) { g_p1[blockIdx.x] = ss[0]; g_p2[blockIdx.x] = sq[0]; }
}

__global__ void k_coef2(const float* __restrict__ gamma, const float* __restrict__ beta) {
    int o = threadIdx.x;
    double s = 0, q = 0;
    for (int n = 0; n < Nn; n++) { s += g_p1[o*32 + n]; q += g_p2[o*32 + n]; }
    double m   = s / (double)(Nn*HW);
    double var = q / (double)(Nn*HW) - m*m;
    float inv  = (float)(1.0 / sqrt(var + 1e-5));
    float A = gamma[o] * inv;
    g_A2[o] = A;
    g_B2[o] = beta[o] - (float)m * A;
}

// ---------------- finalize: bn2 + hardtanh + regularizer scalar ----------------
__global__ void k_final(float* __restrict__ out, const float* __restrict__ reg0, int out_size) {
    size_t idx = (size_t)blockIdx.x * 256 + threadIdx.x;
    if (idx < (size_t)NCHW) {
        int o = (int)((idx >> 10) & 255);
        float v = fmaf(g_z[idx], g_A2[o], g_B2[o]);
        v = fminf(fmaxf(v, -1.f), 1.f);
        out[idx] = v;
    }
    if (idx == 0) out[out_size - 1] = reg0[0] + g_regbase;
}

// ---------------- launch ----------------
extern "C" void kernel_launch(void* const* d_in, const int* in_sizes, int n_in,
                              void* d_out, int out_size) {
    const float* x0   = (const float*)d_in[0];
    const float* reg0 = (const float*)d_in[1];
    const float* w1   = (const float*)d_in[2];
    const float* g1   = (const float*)d_in[3];
    const float* b1   = (const float*)d_in[4];
    const float* w2   = (const float*)d_in[5];
    const float* g2   = (const float*)d_in[6];
    const float* b2   = (const float*)d_in[7];
    float* out = (float*)d_out;

    k_init<<<1, 512>>>();
    k_packw_chan<<<72, 256>>>(w1, 0);
    k_packw_chan<<<72, 256>>>(w2, 1);
    k_packw_r<<<256, 256>>>(w1, 0);
    k_packw_r<<<256, 256>>>(w2, 1);
    k_pack_x<<<Nn*Hh, 256>>>(x0);

    k_conv_int<1><<<Nn*30, 256>>>(nullptr, 0);
    k_conv_bnd<1><<<Nn*124, 256>>>(nullptr, 0);
    k_stats1<<<Cc*Nn, 256>>>();
    k_coef1<<<1, Cc>>>(g1, b1);
    k_pack2<<<Nn*Hh, 256>>>();

    k_conv_int<2><<<Nn*30, 256>>>(x0, 1);
    k_conv_bnd<2><<<Nn*124, 256>>>(x0, 1);
    k_stats2a<<<Cc*Nn, 256>>>();
    k_coef2<<<1, Cc>>>(g2, b2);

    k_final<<<(NCHW + 255) / 256, 256>>>(out, reg0, out_size);
}

// round 3
// speedup vs baseline: 1.5622x; 1.5605x over previous
#include <cuda_runtime.h>
#include <cstdint>

#define Nn 32
#define Cc 256
#define Hh 32
#define Ww 32
#define HW (Hh*Ww)
#define NCHW (Nn*Cc*Hh*Ww)
#define NPIX (Nn*Hh*Ww)
#define NCHUNK 36

// ---------------- scratch (device globals; no allocation) ----------------
__device__ uint32_t           g_xbits[NPIX*8];        // channel-packed sign bits of current conv input
__device__ uint32_t           g_wchan[2][Cc*72];      // channel-packed weights [o][j=0..8][k=0..7]
__device__ unsigned long long g_wrT[2][NCHUNK*Cc];    // r-packed weights, transposed [chunk][o]
__device__ int16_t            g_y1[NCHW];             // conv1 output (clipped int)
__device__ float              g_z[NCHW];              // conv2 output + residual
__device__ int                g_s1[Cc], g_q1[Cc];     // conv1 channel stats (exact int32)
__device__ float              g_A1[Cc], g_B1[Cc];     // bn1 sign-test coefs
__device__ double             g_S2[Cc], g_Q2[Cc];     // bn2 channel stats
__device__ float              g_A2[Cc], g_B2[Cc];
__device__ unsigned long long g_vmask[9*NCHUNK];      // per boundary-class valid-bit mask per chunk
__device__ int                g_V[9*NCHUNK];          // valid counts
__device__ float              g_regbase;              // 3*G/1024

// ---------------- init: geometric tables + stat reset + regularizer ----------------
__global__ void k_init() {
    int t = threadIdx.x;
    if (t < 9*NCHUNK) {
        int cls = t / NCHUNK, i = t % NCHUNK;
        int ht = cls / 3, wt = cls % 3;
        int r = 64*i, c = r/9, j = r - 9*c;
        unsigned long long m = 0;
        for (int b = 0; b < 64; b++) {
            int kh = j/3, kw = j - 3*kh;
            bool inval = (ht==0 && kh==0) || (ht==2 && kh==2) ||
                         (wt==0 && kw==0) || (wt==2 && kw==2);
            if (!inval) m |= 1ull << b;
            if (++j == 9) { j = 0; c++; }
        }
        g_vmask[t] = m;
        g_V[t] = __popcll(m);
    }
    if (t < Cc) { g_s1[t] = 0; g_q1[t] = 0; g_S2[t] = 0.0; g_Q2[t] = 0.0; }
    __syncthreads();
    if (t == 0) {
        // reg = r1 + 2*r2 = 3 * sum_{chunks,pixels} parity / (H*W); parity is geometric
        long long G = 0;
        int npix[3] = {1, 30, 1};
        for (int cls = 0; cls < 9; cls++) {
            long long cnt = (long long)npix[cls/3] * npix[cls%3];
            for (int i = 0; i < NCHUNK; i++)
                G += cnt * (long long)(g_V[cls*NCHUNK + i] & 1);
        }
        g_regbase = 3.0f * (float)G / (float)HW;
    }
}

// ---------------- weight packing: both layouts, both convs, one kernel ----------------
__global__ void k_packw(const float* __restrict__ w1, const float* __restrict__ w2) {
    int o    = blockIdx.x & 255;
    int slot = blockIdx.x >> 8;
    const float* w = slot ? w2 : w1;
    int warp = threadIdx.x >> 5, lane = threadIdx.x & 31;

    // r-packed transposed: bit b of word [i][o] = sign(w[o, r=64i+b])
    for (int i = warp; i < NCHUNK; i += 8) {
        unsigned lo = __ballot_sync(0xffffffffu, w[o*2304 + 64*i + lane]      >= 0.f);
        unsigned hi = __ballot_sync(0xffffffffu, w[o*2304 + 64*i + 32 + lane] >= 0.f);
        if (lane == 0)
            g_wrT[slot][i*Cc + o] = (unsigned long long)lo | ((unsigned long long)hi << 32);
    }

    // channel-packed: word [o][j][c>>5], bit (c&31)
    int c = threadIdx.x;
    float v[9];
    #pragma unroll
    for (int j = 0; j < 9; j++) v[j] = w[o*2304 + c*9 + j];
    #pragma unroll
    for (int j = 0; j < 9; j++) {
        unsigned b = __ballot_sync(0xffffffffu, v[j] >= 0.f);
        if (lane == 0) g_wchan[slot][o*72 + j*8 + (c >> 5)] = b;
    }
}

// ---------------- input packing ----------------
__global__ void k_pack_x(const float* __restrict__ x) {
    int n = blockIdx.x >> 5, h = blockIdx.x & 31;
    int w = threadIdx.x & 31, k = threadIdx.x >> 5;
    const float* base = x + ((size_t)(n*Cc + k*32) * Hh + h) * Ww + w;
    uint32_t word = 0;
    #pragma unroll 8
    for (int cc = 0; cc < 32; cc++)
        if (base[(size_t)cc * HW] >= 0.f) word |= 1u << cc;
    g_xbits[((n*Hh + h)*Ww + w)*8 + k] = word;
}

// pack sign of bn1(hardtanh preserves sign): bit = (y*A1[c] + B1[c] >= 0)
__global__ void k_pack2() {
    int n = blockIdx.x >> 5, h = blockIdx.x & 31;
    int w = threadIdx.x & 31, k = threadIdx.x >> 5;
    const int16_t* base = g_y1 + ((size_t)(n*Cc + k*32) * Hh + h) * Ww + w;
    uint32_t word = 0;
    #pragma unroll 8
    for (int cc = 0; cc < 32; cc++) {
        int c = k*32 + cc;
        float y = (float)base[(size_t)cc * HW];
        if (fmaf(y, g_A1[c], g_B1[c]) >= 0.f) word |= 1u << cc;
    }
    g_xbits[((n*Hh + h)*Ww + w)*8 + k] = word;
}

__device__ __forceinline__ int popc8(uint4 xa, uint4 xb, uint4 wa, uint4 wb) {
    return __popc(xa.x ^ wa.x) + __popc(xa.y ^ wa.y)
         + __popc(xa.z ^ wa.z) + __popc(xa.w ^ wa.w)
         + __popc(xb.x ^ wb.x) + __popc(xb.y ^ wb.y)
         + __popc(xb.z ^ wb.z) + __popc(xb.w ^ wb.w);
}

// ---------------- interior conv: 2-row strip, fused BN stats ----------------
// quantization is an exact no-op for interior pixels (psum always even, |psum|<=64)
template<int MODE>   // 1: write y1 int16 + int stats; 2: write z = clipped + residual + float stats
__global__ void k_conv_int(const float* __restrict__ x0res, int slot) {
    int n = blockIdx.x / 15, hp = blockIdx.x % 15;
    int h0 = 1 + 2*hp;                       // rows h0, h0+1; halo rows h0-1..h0+2
    __shared__ __align__(16) uint32_t sx[4][Ww][8];
    int t = threadIdx.x;
    ((uint4*)sx)[t] = ((const uint4*)(g_xbits + (size_t)(n*Hh + (h0-1)) * Ww * 8))[t];
    __syncthreads();

    int w = t & 31, warp = t >> 5;
    int wl = (w > 0) ? w-1 : 0;
    int wr = (w < 31) ? w+1 : 31;
    const int wcol[3] = {wl, w, wr};
    bool valid = (w >= 1 && w <= 30);
    size_t base0 = (((size_t)n*Cc*Hh) + h0) * Ww + w;   // + o*HW

    for (int og = 0; og < 32; og++) {
        int o = og*8 + warp;
        const uint4* wp = (const uint4*)(&g_wchan[slot][o*72]);
        int s0 = 0, s1 = 0;
        #pragma unroll
        for (int j = 0; j < 9; j++) {
            int rr = j / 3;
            int wc = wcol[j % 3];
            uint4 wa = __ldg(wp + 2*j);
            uint4 wb = __ldg(wp + 2*j + 1);
            const uint32_t* xp0 = &sx[rr][wc][0];
            uint4 xa = *(const uint4*)xp0;
            uint4 xb = *(const uint4*)(xp0 + 4);
            s0 += popc8(xa, xb, wa, wb);
            const uint32_t* xp1 = &sx[rr+1][wc][0];
            uint4 ya = *(const uint4*)xp1;
            uint4 yb = *(const uint4*)(xp1 + 4);
            s1 += popc8(ya, yb, wa, wb);
        }
        int a0 = min(max(2304 - 2*s0, -254), 254);
        int a1 = min(max(2304 - 2*s1, -254), 254);
        size_t idx = base0 + (size_t)o * HW;
        if (MODE == 1) {
            if (valid) { g_y1[idx] = (int16_t)a0; g_y1[idx + Ww] = (int16_t)a1; }
            int vs = valid ? (a0 + a1) : 0;
            int vq = valid ? (a0*a0 + a1*a1) : 0;
            vs = __reduce_add_sync(0xffffffffu, vs);
            vq = __reduce_add_sync(0xffffffffu, vq);
            if (w == 0) { atomicAdd(&g_s1[o], vs); atomicAdd(&g_q1[o], vq); }
        } else {
            float z0 = 0.f, z1 = 0.f;
            if (valid) {
                z0 = (float)a0 + x0res[idx];
                z1 = (float)a1 + x0res[idx + Ww];
                g_z[idx] = z0; g_z[idx + Ww] = z1;
            }
            float fs = z0 + z1, fq = z0*z0 + z1*z1;
            #pragma unroll
            for (int d = 16; d; d >>= 1) {
                fs += __shfl_xor_sync(0xffffffffu, fs, d);
                fq += __shfl_xor_sync(0xffffffffu, fq, d);
            }
            if (w == 0) { atomicAdd(&g_S2[o], (double)fs); atomicAdd(&g_Q2[o], (double)fq); }
        }
    }
}

// ---------------- boundary conv: exact chunked psum, banker's rounding, fused stats ----------------
template<int MODE>
__global__ void k_conv_bnd(const float* __restrict__ x0res, int slot) {
    int n = blockIdx.x / 124, b = blockIdx.x % 124;
    int h, w;
    if      (b < 32) { h = 0;      w = b; }
    else if (b < 64) { h = 31;     w = b - 32; }
    else if (b < 94) { w = 0;      h = b - 63; }
    else             { w = 31;     h = b - 93; }
    int ht  = (h == 0) ? 0 : ((h == 31) ? 2 : 1);
    int wt  = (w == 0) ? 0 : ((w == 31) ? 2 : 1);
    int cls = ht*3 + wt;

    __shared__ unsigned long long sxr[NCHUNK];
    __shared__ int soff[9];
    int t = threadIdx.x;
    if (t < 9) {
        int kh = t / 3, kw = t % 3;
        int hh = min(max(h + kh - 1, 0), 31);
        int ww = min(max(w + kw - 1, 0), 31);
        soff[t] = ((n*Hh + hh)*Ww + ww) * 8;
    }
    __syncthreads();
    if (t < NCHUNK) {   // build r-ordered bit word for this chunk
        int i = t, r = 64*i, c = r/9, j = r - 9*c;
        unsigned long long word = 0;
        for (int bb = 0; bb < 64; bb++) {
            uint32_t xw = g_xbits[soff[j] + (c >> 5)];
            word |= (unsigned long long)((xw >> (c & 31)) & 1u) << bb;
            if (++j == 9) { j = 0; c++; }
        }
        sxr[i] = word;
    }
    __syncthreads();

    int o = t;   // 256 threads = 256 output channels
    int acc = 0;
    #pragma unroll 4
    for (int i = 0; i < NCHUNK; i++) {
        unsigned long long X = (sxr[i] ^ g_wrT[slot][i*Cc + o]) & g_vmask[cls*NCHUNK + i];
        int psum = g_V[cls*NCHUNK + i] - 2*__popcll(X);
        int rmod = psum & 3;                   // two's-complement mod 4
        psum += (rmod == 3) - (rmod == 1);     // round-half-to-even of psum/2, *2
        acc += psum;
    }
    acc = min(max(acc, -254), 254);
    size_t idx = ((size_t)(n*Cc + o) * Hh + h) * Ww + w;
    if (MODE == 1) {
        g_y1[idx] = (int16_t)acc;
        atomicAdd(&g_s1[o], acc);
        atomicAdd(&g_q1[o], acc*acc);
    } else {
        float z = (float)acc + x0res[idx];
        g_z[idx] = z;
        atomicAdd(&g_S2[o], (double)z);
        atomicAdd(&g_Q2[o], (double)(z*z));
    }
}

// ---------------- BN coefficient kernels ----------------
__global__ void k_coef1(const float* __restrict__ gamma, const float* __restrict__ beta) {
    int o = threadIdx.x;
    double m   = (double)g_s1[o] / (double)(Nn*HW);
    double var = (double)g_q1[o] / (double)(Nn*HW) - m*m;
    float inv  = (float)(1.0 / sqrt(var + 1e-5));
    float A = gamma[o] * inv;
    g_A1[o] = A;
    g_B1[o] = beta[o] - (float)m * A;
}

__global__ void k_coef2(const float* __restrict__ gamma, const float* __restrict__ beta) {
    int o = threadIdx.x;
    double m   = g_S2[o] / (double)(Nn*HW);
    double var = g_Q2[o] / (double)(Nn*HW) - m*m;
    float inv  = (float)(1.0 / sqrt(var + 1e-5));
    float A = gamma[o] * inv;
    g_A2[o] = A;
    g_B2[o] = beta[o] - (float)m * A;
}

// ---------------- finalize: bn2 + hardtanh + regularizer scalar (float4 vectorized) ----------------
__global__ void k_final(float* __restrict__ out, const float* __restrict__ reg0, int out_size) {
    size_t v = (size_t)blockIdx.x * 256 + threadIdx.x;   // float4 index
    size_t idx = v * 4;
    if (idx < (size_t)NCHW) {
        int o = (int)((idx >> 10) & 255);
        float A = g_A2[o], B = g_B2[o];
        float4 z = *(const float4*)(g_z + idx);
        float4 r;
        r.x = fminf(fmaxf(fmaf(z.x, A, B), -1.f), 1.f);
        r.y = fminf(fmaxf(fmaf(z.y, A, B), -1.f), 1.f);
        r.z = fminf(fmaxf(fmaf(z.z, A, B), -1.f), 1.f);
        r.w = fminf(fmaxf(fmaf(z.w, A, B), -1.f), 1.f);
        *(float4*)(out + idx) = r;
    }
    if (v == 0) out[out_size - 1] = reg0[0] + g_regbase;
}

// ---------------- launch ----------------
extern "C" void kernel_launch(void* const* d_in, const int* in_sizes, int n_in,
                              void* d_out, int out_size) {
    const float* x0   = (const float*)d_in[0];
    const float* reg0 = (const float*)d_in[1];
    const float* w1   = (const float*)d_in[2];
    const float* g1   = (const float*)d_in[3];
    const float* b1   = (const float*)d_in[4];
    const float* w2   = (const float*)d_in[5];
    const float* g2   = (const float*)d_in[6];
    const float* b2   = (const float*)d_in[7];
    float* out = (float*)d_out;

    k_init<<<1, 512>>>();                       // 0
    k_packw<<<512, 256>>>(w1, w2);              // 1
    k_pack_x<<<Nn*Hh, 256>>>(x0);               // 2
    k_conv_int<1><<<Nn*15, 256>>>(nullptr, 0);  // 3  <- ncu -s 5 target
    k_conv_bnd<1><<<Nn*124, 256>>>(nullptr, 0); // 4  <- or this one
    k_coef1<<<1, Cc>>>(g1, b1);                 // 5
    k_pack2<<<Nn*Hh, 256>>>();                  // 6
    k_conv_int<2><<<Nn*15, 256>>>(x0, 1);       // 7
    k_conv_bnd<2><<<Nn*124, 256>>>(x0, 1);      // 8
    k_coef2<<<1, Cc>>>(g2, b2);                 // 9
    k_final<<<(NCHW/4 + 255) / 256, 256>>>(out, reg0, out_size);  // 10
}